// round 4
// baseline (speedup 1.0000x reference)
#include <cuda_runtime.h>
#include <cstdint>

// LinearPositionInterpolation — segment-parallel + bulk-async (TMA) stores.
//   index: (n,) int32 sorted keypoints (n=129, uniform spacing 32 here)
//   value: (batch, n, dim) fp32   (32, 129, 256)
//   out:   (batch, m, dim) fp32, m = index[n-1]-index[0] = 4096
//
// R2 post-mortem: STG.128 path left L1tex as top consumer (61%) with DRAM
// only 46%. This version computes 16-row tiles into SMEM and drains them with
// cp.async.bulk.global.shared::cta (linear 16KB bulk copies, bypassing L1),
// double-buffered so SMEM fill overlaps the async drain. Each CTA handles one
// (segment, batch): its output is a contiguous 32KB region.

#define DIM      256
#define DIM4     (DIM / 4)        // 64 float4 columns
#define ROWS     4                // row-groups per CTA
#define BLOCK    (ROWS * DIM4)    // 256 threads
#define TILE_R   16               // rows per bulk-store tile (16 KB)

__global__ __launch_bounds__(BLOCK)
void lpi_tma_kernel(const int* __restrict__ index,
                    const float4* __restrict__ value,
                    float4* __restrict__ out,
                    int n, int m)
{
    __shared__ __align__(128) float4 buf[2][TILE_R * DIM4];   // 2 x 16 KB

    const int s  = blockIdx.x;                // segment 0..n-2
    const int b  = blockIdx.y;                // batch
    const int d  = threadIdx.x & (DIM4 - 1);  // float4 column
    const int rg = threadIdx.x >> 6;          // row-group 0..ROWS-1

    const int base = __ldg(&index[0]);
    const int x0   = __ldg(&index[s])     - base;
    const int x1   = __ldg(&index[s + 1]) - base;
    const int L    = x1 - x0;                 // segment length (32 here)
    const float invL = 1.0f / (float)L;

    const long long vrow = ((long long)b * n + s) * DIM4 + d;
    const float4 y0 = value[vrow];
    const float4 y1 = value[vrow + DIM4];
    const float4 dy = make_float4(y1.x - y0.x, y1.y - y0.y,
                                  y1.z - y0.z, y1.w - y0.w);

    // Contiguous output region for this (b, segment): rows x0 .. x1-1.
    float4* obase = out + ((long long)b * m + x0) * DIM4;

    int buf_id = 0;
    for (int r0 = 0; r0 < L; r0 += TILE_R) {
        const int rows = min(TILE_R, L - r0);

        // Compute this tile into SMEM. Warp-wide STS.128, conflict-free.
        for (int r = rg; r < rows; r += ROWS) {
            const float w = (float)(r0 + r + 1) * invL;
            float4 o;
            o.x = fmaf(dy.x, w, y0.x);
            o.y = fmaf(dy.y, w, y0.y);
            o.z = fmaf(dy.z, w, y0.z);
            o.w = fmaf(dy.w, w, y0.w);
            buf[buf_id][r * DIM4 + d] = o;
        }
        __syncthreads();

        if (threadIdx.x == 0) {
            // Make CTA's generic-proxy SMEM writes visible to the async proxy,
            // then issue one linear bulk store (rows * 1024 bytes).
            asm volatile("fence.proxy.async.shared::cta;" ::: "memory");
            uint32_t src = (uint32_t)__cvta_generic_to_shared(&buf[buf_id][0]);
            asm volatile(
                "cp.async.bulk.global.shared::cta.bulk_group [%0], [%1], %2;"
                :: "l"(obase + (long long)r0 * DIM4), "r"(src),
                   "r"(rows * DIM * 4)
                : "memory");
            asm volatile("cp.async.bulk.commit_group;" ::: "memory");
            // Allow at most 1 group in flight so the buffer we are about to
            // refill has been fully read by the async engine.
            asm volatile("cp.async.bulk.wait_group.read 1;" ::: "memory");
        }
        buf_id ^= 1;
        __syncthreads();
    }

    // Drain all outstanding bulk stores before CTA exit.
    if (threadIdx.x == 0)
        asm volatile("cp.async.bulk.wait_group 0;" ::: "memory");
}

extern "C" void kernel_launch(void* const* d_in, const int* in_sizes, int n_in,
                              void* d_out, int out_size)
{
    const int*   index = (const int*)d_in[0];
    const float* value = (const float*)d_in[1];
    float*       outp  = (float*)d_out;

    int n = in_sizes[0];                                   // 129
    long long velems = in_sizes[1];
    int batch = (int)(velems / ((long long)n * DIM));      // 32
    int m = (int)((long long)out_size / ((long long)batch * DIM)); // 4096

    dim3 grid(n - 1, batch);             // (128, 32) = 4096 CTAs
    dim3 block(BLOCK);                   // 256 threads

    lpi_tma_kernel<<<grid, block>>>(index,
                                    (const float4*)value,
                                    (float4*)outp,
                                    n, m);
}

// round 5
// speedup vs baseline: 1.1015x; 1.1015x over previous
#include <cuda_runtime.h>
#include <cstdint>

// LinearPositionInterpolation — segment-parallel, direct streaming stores.
//   index: (n,) int32 sorted keypoints (n=129, uniform spacing 32 here)
//   value: (batch, n, dim) fp32   (32, 129, 256)
//   out:   (batch, m, dim) fp32, m = index[n-1]-index[0] = 4096
//
// R4 post-mortem: SMEM+cp.async.bulk store path was neutral (same L1 port
// pays STS + bulk read). Direct STG.128 wins. This round:
//   - __stcs streaming stores (evict-first): output is written once, never
//     re-read; avoid thrashing L2 (output 134MB > L2 126MB).
//   - loop-incremental w (removes I2F+FMUL dependent chain per iteration).
//   - fully unrolled fast path for segment length 32 (this dataset).

#define DIM    256
#define DIM4   (DIM / 4)          // 64 float4 columns per row
#define ROWS   4                  // row-groups per CTA
#define BLOCK  (ROWS * DIM4)      // 256 threads

__global__ __launch_bounds__(BLOCK)
void lpi_seg_kernel(const int* __restrict__ index,
                    const float4* __restrict__ value,
                    float4* __restrict__ out,
                    int n, int m)
{
    const int s  = blockIdx.x;                 // segment 0..n-2
    const int b  = blockIdx.y;                 // batch
    const int d  = threadIdx.x & (DIM4 - 1);   // float4 column
    const int rg = threadIdx.x >> 6;           // row-group 0..ROWS-1

    const int base = __ldg(&index[0]);
    const int x0   = __ldg(&index[s])     - base;
    const int x1   = __ldg(&index[s + 1]) - base;
    const int L    = x1 - x0;
    const float invL = 1.0f / (float)L;

    const long long vrow = ((long long)b * n + s) * DIM4 + d;
    const float4 y0 = value[vrow];
    const float4 y1 = value[vrow + DIM4];
    const float4 dy = make_float4(y1.x - y0.x, y1.y - y0.y,
                                  y1.z - y0.z, y1.w - y0.w);

    float4* orow = out + ((long long)b * m + x0 + rg) * DIM4 + d;
    const int ostep = ROWS * DIM4;

    // w for row-group rg starts at (rg+1)*invL and advances ROWS*invL.
    float w = (float)(rg + 1) * invL;
    const float wstep = (float)ROWS * invL;

    if (L == 32) {
        // Fast path: 8 iterations, fully unrolled, streaming stores.
        #pragma unroll
        for (int it = 0; it < 32 / ROWS; ++it) {
            float4 o;
            o.x = fmaf(dy.x, w, y0.x);
            o.y = fmaf(dy.y, w, y0.y);
            o.z = fmaf(dy.z, w, y0.z);
            o.w = fmaf(dy.w, w, y0.w);
            __stcs(orow, o);
            orow += ostep;
            w += wstep;
        }
    } else {
        for (int p = x0 + 1 + rg; p <= x1; p += ROWS) {
            float4 o;
            o.x = fmaf(dy.x, w, y0.x);
            o.y = fmaf(dy.y, w, y0.y);
            o.z = fmaf(dy.z, w, y0.z);
            o.w = fmaf(dy.w, w, y0.w);
            __stcs(orow, o);
            orow += ostep;
            w += wstep;
        }
    }
}

extern "C" void kernel_launch(void* const* d_in, const int* in_sizes, int n_in,
                              void* d_out, int out_size)
{
    const int*   index = (const int*)d_in[0];
    const float* value = (const float*)d_in[1];
    float*       outp  = (float*)d_out;

    int n = in_sizes[0];                                   // 129
    long long velems = in_sizes[1];
    int batch = (int)(velems / ((long long)n * DIM));      // 32
    int m = (int)((long long)out_size / ((long long)batch * DIM)); // 4096

    dim3 grid(n - 1, batch);             // (128, 32) = 4096 CTAs
    dim3 block(BLOCK);                   // 256 threads

    lpi_seg_kernel<<<grid, block>>>(index,
                                    (const float4*)value,
                                    (float4*)outp,
                                    n, m);
}